// round 1
// baseline (speedup 1.0000x reference)
#include <cuda_runtime.h>
#include <cstdint>
#include <cstddef>

#define N_NODES 50000
#define N_EDGES 800000
#define D_NODE  64
#define D_MSG   128

// Scratch (device globals; no allocation in kernel_launch).
// g_P layout per node: [0:128)=ns@W1_f[0:64]   (pair with from, fwd)
//                      [128:256)=ns@W1_f[64:128] (pair with to, fwd)
//                      [256:384)=ns@W1_r[0:64]   (pair with to, rev)
//                      [384:512)=ns@W1_r[64:128] (pair with from, rev)
__device__ float g_P[(size_t)N_NODES * 512];
__device__ float g_agg[(size_t)N_NODES * D_MSG];

__device__ __forceinline__ void red_add_v4(float* p, float a, float b, float c, float d) {
    asm volatile("red.global.add.v4.f32 [%0], {%1, %2, %3, %4};"
                 :: "l"(p), "f"(a), "f"(b), "f"(c), "f"(d) : "memory");
}

// ---------------------------------------------------------------------------
// Zero the aggregation buffer (graph-replay safe: done every launch).
// ---------------------------------------------------------------------------
__global__ void k_zero() {
    const int n4 = N_NODES * D_MSG / 4;
    float4 z = make_float4(0.f, 0.f, 0.f, 0.f);
    for (int i = blockIdx.x * blockDim.x + threadIdx.x; i < n4; i += gridDim.x * blockDim.x)
        ((float4*)g_agg)[i] = z;
}

// ---------------------------------------------------------------------------
// Node pre-projections: g_P = ns @ [W1_f[0:64] | W1_f[64:128] | W1_r[0:64] | W1_r[64:128]]
// Tile: 32 nodes per block, 256 threads. Static smem.
// ---------------------------------------------------------------------------
__global__ __launch_bounds__(256) void k_pre(const float* __restrict__ ns,
                                             const float* __restrict__ W1f,
                                             const float* __restrict__ W1r) {
    __shared__ float s_x[32 * 64];    // 8 KB
    __shared__ float s_w[64 * 128];   // 32 KB
    const int t = threadIdx.x;
    const int base = blockIdx.x * 32;

    // stage node tile (zero-filled past N_NODES)
    for (int i = t; i < 512; i += 256) {           // 2048 floats = 512 float4
        int n = base + i / 16;
        float4 v = make_float4(0.f, 0.f, 0.f, 0.f);
        if (n < N_NODES) v = ((const float4*)ns)[(size_t)n * 16 + (i % 16)];
        ((float4*)s_x)[i] = v;
    }

    const int tx = t % 32, ty = t / 32;
    const int j0 = tx * 4, n0 = ty * 4;

    for (int m = 0; m < 4; ++m) {
        __syncthreads();
        const float* Wsrc = ((m < 2) ? W1f : W1r) + (size_t)(m & 1) * 64 * 128;
        for (int i = t; i < 2048; i += 256)        // 8192 floats = 2048 float4
            ((float4*)s_w)[i] = ((const float4*)Wsrc)[i];
        __syncthreads();

        float acc[4][4] = {};
        for (int k4 = 0; k4 < 16; ++k4) {
            float4 xv[4];
            #pragma unroll
            for (int n = 0; n < 4; ++n)
                xv[n] = *(const float4*)&s_x[(n0 + n) * 64 + k4 * 4];
            #pragma unroll
            for (int kk = 0; kk < 4; ++kk) {
                float4 w = *(const float4*)&s_w[(k4 * 4 + kk) * 128 + j0];
                #pragma unroll
                for (int n = 0; n < 4; ++n) {
                    float x = ((const float*)&xv[n])[kk];
                    acc[n][0] += x * w.x; acc[n][1] += x * w.y;
                    acc[n][2] += x * w.z; acc[n][3] += x * w.w;
                }
            }
        }
        #pragma unroll
        for (int n = 0; n < 4; ++n) {
            int gn = base + n0 + n;
            if (gn < N_NODES)
                *(float4*)&g_P[(size_t)gn * 512 + m * 128 + j0] =
                    make_float4(acc[n][0], acc[n][1], acc[n][2], acc[n][3]);
        }
    }
}

// ---------------------------------------------------------------------------
// Edge kernel: per 128-edge tile, both directions.
//   h = relu(P_A[idxA] + P_B[idxB] + ef @ W1[128:192] + b1)
//   msg = h @ W2 + b2 ; red-add into g_agg[idxB]
// 256 threads; each thread owns an 8-edge x 8-col register tile.
// ---------------------------------------------------------------------------
#define EDGE_SMEM (49152 * 4 + 256 * 4)
__global__ __launch_bounds__(256) void k_edge(
    const float* __restrict__ ef,
    const float* __restrict__ W1f, const float* __restrict__ b1f,
    const float* __restrict__ W2f, const float* __restrict__ b2f,
    const float* __restrict__ W1r, const float* __restrict__ b1r,
    const float* __restrict__ W2r, const float* __restrict__ b2r,
    const int* __restrict__ from_idx, const int* __restrict__ to_idx) {
    extern __shared__ float sm[];
    float* s_ef = sm;              // 128x64   = 8192
    float* s_w1 = sm + 8192;       // 64x128   = 8192
    float* s_w2 = sm + 16384;      // 128x128  = 16384
    float* s_h  = sm + 32768;      // 128x128  = 16384
    int*   s_from = (int*)(sm + 49152);
    int*   s_to   = s_from + 128;

    const int t = threadIdx.x;
    const int ebase = blockIdx.x * 128;   // N_EDGES % 128 == 0

    // stage edge features (contiguous rows) + indices
    for (int i = t; i < 2048; i += 256)
        ((float4*)s_ef)[i] = ((const float4*)(ef + (size_t)ebase * 64))[i];
    if (t < 128) s_from[t] = from_idx[ebase + t];
    else         s_to[t - 128] = to_idx[ebase + t - 128];

    const int tx = t % 16, ty = t / 16;
    const int j0 = tx * 8, e0 = ty * 8;

    for (int dir = 0; dir < 2; ++dir) {
        const float* W1 = dir ? W1r : W1f;
        const float* W2 = dir ? W2r : W2f;
        const float* b1 = dir ? b1r : b1f;
        const float* b2 = dir ? b2r : b2f;
        const int offA = dir * 256;

        __syncthreads();   // previous phase done before weights overwritten
        for (int i = t; i < 2048; i += 256)
            ((float4*)s_w1)[i] = ((const float4*)(W1 + 128 * 128))[i];
        for (int i = t; i < 4096; i += 256)
            ((float4*)s_w2)[i] = ((const float4*)W2)[i];
        __syncthreads();

        // ---- layer 1: ef @ W1c ----
        float acc[8][8] = {};
        for (int k4 = 0; k4 < 16; ++k4) {
            float4 xv[8];
            #pragma unroll
            for (int e = 0; e < 8; ++e)
                xv[e] = *(const float4*)&s_ef[(e0 + e) * 64 + k4 * 4];
            #pragma unroll
            for (int kk = 0; kk < 4; ++kk) {
                float4 w0 = *(const float4*)&s_w1[(k4 * 4 + kk) * 128 + j0];
                float4 w1 = *(const float4*)&s_w1[(k4 * 4 + kk) * 128 + j0 + 4];
                #pragma unroll
                for (int e = 0; e < 8; ++e) {
                    float x = ((const float*)&xv[e])[kk];
                    acc[e][0] += x * w0.x; acc[e][1] += x * w0.y;
                    acc[e][2] += x * w0.z; acc[e][3] += x * w0.w;
                    acc[e][4] += x * w1.x; acc[e][5] += x * w1.y;
                    acc[e][6] += x * w1.z; acc[e][7] += x * w1.w;
                }
            }
        }
        // ---- add gathered node pre-projections + bias, relu, -> smem ----
        float4 bb0 = *(const float4*)&b1[j0];
        float4 bb1 = *(const float4*)&b1[j0 + 4];
        #pragma unroll
        for (int e = 0; e < 8; ++e) {
            int ee = e0 + e;
            int ia = dir ? s_to[ee] : s_from[ee];
            int ib = dir ? s_from[ee] : s_to[ee];
            const float* pA = g_P + (size_t)ia * 512 + offA + j0;
            const float* pB = g_P + (size_t)ib * 512 + offA + 128 + j0;
            float4 a0 = *(const float4*)pA, a1 = *(const float4*)(pA + 4);
            float4 c0 = *(const float4*)pB, c1 = *(const float4*)(pB + 4);
            float v0 = fmaxf(acc[e][0] + a0.x + c0.x + bb0.x, 0.f);
            float v1 = fmaxf(acc[e][1] + a0.y + c0.y + bb0.y, 0.f);
            float v2 = fmaxf(acc[e][2] + a0.z + c0.z + bb0.z, 0.f);
            float v3 = fmaxf(acc[e][3] + a0.w + c0.w + bb0.w, 0.f);
            float v4 = fmaxf(acc[e][4] + a1.x + c1.x + bb1.x, 0.f);
            float v5 = fmaxf(acc[e][5] + a1.y + c1.y + bb1.y, 0.f);
            float v6 = fmaxf(acc[e][6] + a1.z + c1.z + bb1.z, 0.f);
            float v7 = fmaxf(acc[e][7] + a1.w + c1.w + bb1.w, 0.f);
            *(float4*)&s_h[ee * 128 + j0]     = make_float4(v0, v1, v2, v3);
            *(float4*)&s_h[ee * 128 + j0 + 4] = make_float4(v4, v5, v6, v7);
        }
        __syncthreads();

        // ---- layer 2: h @ W2 ----
        float acc2[8][8] = {};
        for (int k4 = 0; k4 < 32; ++k4) {
            float4 xv[8];
            #pragma unroll
            for (int e = 0; e < 8; ++e)
                xv[e] = *(const float4*)&s_h[(e0 + e) * 128 + k4 * 4];
            #pragma unroll
            for (int kk = 0; kk < 4; ++kk) {
                float4 w0 = *(const float4*)&s_w2[(k4 * 4 + kk) * 128 + j0];
                float4 w1 = *(const float4*)&s_w2[(k4 * 4 + kk) * 128 + j0 + 4];
                #pragma unroll
                for (int e = 0; e < 8; ++e) {
                    float x = ((const float*)&xv[e])[kk];
                    acc2[e][0] += x * w0.x; acc2[e][1] += x * w0.y;
                    acc2[e][2] += x * w0.z; acc2[e][3] += x * w0.w;
                    acc2[e][4] += x * w1.x; acc2[e][5] += x * w1.y;
                    acc2[e][6] += x * w1.z; acc2[e][7] += x * w1.w;
                }
            }
        }
        // ---- scatter (msg + b2) into g_agg[ib] ----
        float4 cb0 = *(const float4*)&b2[j0];
        float4 cb1 = *(const float4*)&b2[j0 + 4];
        #pragma unroll
        for (int e = 0; e < 8; ++e) {
            int ee = e0 + e;
            int ib = dir ? s_from[ee] : s_to[ee];
            float* p = g_agg + (size_t)ib * 128 + j0;
            red_add_v4(p,     acc2[e][0] + cb0.x, acc2[e][1] + cb0.y,
                              acc2[e][2] + cb0.z, acc2[e][3] + cb0.w);
            red_add_v4(p + 4, acc2[e][4] + cb1.x, acc2[e][5] + cb1.y,
                              acc2[e][6] + cb1.z, acc2[e][7] + cb1.w);
        }
    }
}

// ---------------------------------------------------------------------------
// Node update: out = ns + relu([agg | ns] @ Wn1 + bn1) @ Wn2 + bn2
// Tile: 64 nodes / block, 256 threads, dynamic smem.
// ---------------------------------------------------------------------------
#define NODE_SMEM (53248 * 4)
__global__ __launch_bounds__(256) void k_node(
    const float* __restrict__ ns,
    const float* __restrict__ Wn1, const float* __restrict__ bn1,
    const float* __restrict__ Wn2, const float* __restrict__ bn2,
    float* __restrict__ out) {
    extern __shared__ float sm[];
    float* s_x  = sm;             // 64x192 = 12288
    float* s_w1 = sm + 12288;     // 192x128 = 24576
    float* s_h  = sm + 36864;     // 64x128 = 8192
    float* s_w2 = sm + 45056;     // 128x64 = 8192

    const int t = threadIdx.x;
    const int base = blockIdx.x * 64;

    // stage x = [agg(128) | ns(64)] (zero-filled past N_NODES)
    for (int i = t; i < 3072; i += 256) {        // 12288 floats = 3072 float4
        int n = i / 48, c4 = i % 48;
        int gn = base + n;
        float4 v = make_float4(0.f, 0.f, 0.f, 0.f);
        if (gn < N_NODES) {
            if (c4 < 32) v = ((const float4*)g_agg)[(size_t)gn * 32 + c4];
            else         v = ((const float4*)ns)[(size_t)gn * 16 + (c4 - 32)];
        }
        ((float4*)s_x)[i] = v;
    }
    for (int i = t; i < 6144; i += 256) ((float4*)s_w1)[i] = ((const float4*)Wn1)[i];
    for (int i = t; i < 2048; i += 256) ((float4*)s_w2)[i] = ((const float4*)Wn2)[i];
    __syncthreads();

    // GEMM1: h[64][128]
    {
        const int tx = t % 32, ty = t / 32;
        const int j0 = tx * 4, n0 = ty * 8;
        float acc[8][4] = {};
        for (int k4 = 0; k4 < 48; ++k4) {
            float4 xv[8];
            #pragma unroll
            for (int n = 0; n < 8; ++n)
                xv[n] = *(const float4*)&s_x[(n0 + n) * 192 + k4 * 4];
            #pragma unroll
            for (int kk = 0; kk < 4; ++kk) {
                float4 w = *(const float4*)&s_w1[(k4 * 4 + kk) * 128 + j0];
                #pragma unroll
                for (int n = 0; n < 8; ++n) {
                    float x = ((const float*)&xv[n])[kk];
                    acc[n][0] += x * w.x; acc[n][1] += x * w.y;
                    acc[n][2] += x * w.z; acc[n][3] += x * w.w;
                }
            }
        }
        float4 bb = *(const float4*)&bn1[j0];
        #pragma unroll
        for (int n = 0; n < 8; ++n) {
            *(float4*)&s_h[(n0 + n) * 128 + j0] = make_float4(
                fmaxf(acc[n][0] + bb.x, 0.f), fmaxf(acc[n][1] + bb.y, 0.f),
                fmaxf(acc[n][2] + bb.z, 0.f), fmaxf(acc[n][3] + bb.w, 0.f));
        }
    }
    __syncthreads();

    // GEMM2 + residual: out[64][64]
    {
        const int tx = t % 16, ty = t / 16;
        const int j0 = tx * 4, n0 = ty * 4;
        float acc[4][4] = {};
        for (int k4 = 0; k4 < 32; ++k4) {
            float4 xv[4];
            #pragma unroll
            for (int n = 0; n < 4; ++n)
                xv[n] = *(const float4*)&s_h[(n0 + n) * 128 + k4 * 4];
            #pragma unroll
            for (int kk = 0; kk < 4; ++kk) {
                float4 w = *(const float4*)&s_w2[(k4 * 4 + kk) * 64 + j0];
                #pragma unroll
                for (int n = 0; n < 4; ++n) {
                    float x = ((const float*)&xv[n])[kk];
                    acc[n][0] += x * w.x; acc[n][1] += x * w.y;
                    acc[n][2] += x * w.z; acc[n][3] += x * w.w;
                }
            }
        }
        float4 bb = *(const float4*)&bn2[j0];
        #pragma unroll
        for (int n = 0; n < 4; ++n) {
            int gn = base + n0 + n;
            if (gn < N_NODES) {
                float4 r = ((const float4*)ns)[(size_t)gn * 16 + j0 / 4];
                ((float4*)out)[(size_t)gn * 16 + j0 / 4] = make_float4(
                    r.x + acc[n][0] + bb.x, r.y + acc[n][1] + bb.y,
                    r.z + acc[n][2] + bb.z, r.w + acc[n][3] + bb.w);
            }
        }
    }
}

// ---------------------------------------------------------------------------
extern "C" void kernel_launch(void* const* d_in, const int* in_sizes, int n_in,
                              void* d_out, int out_size) {
    const float* ns  = (const float*)d_in[0];
    const float* ef  = (const float*)d_in[1];
    const float* W1f = (const float*)d_in[2];
    const float* b1f = (const float*)d_in[3];
    const float* W2f = (const float*)d_in[4];
    const float* b2f = (const float*)d_in[5];
    const float* W1r = (const float*)d_in[6];
    const float* b1r = (const float*)d_in[7];
    const float* W2r = (const float*)d_in[8];
    const float* b2r = (const float*)d_in[9];
    const float* Wn1 = (const float*)d_in[10];
    const float* bn1 = (const float*)d_in[11];
    const float* Wn2 = (const float*)d_in[12];
    const float* bn2 = (const float*)d_in[13];
    const int* from_idx = (const int*)d_in[14];
    const int* to_idx   = (const int*)d_in[15];
    float* out = (float*)d_out;

    cudaFuncSetAttribute(k_edge, cudaFuncAttributeMaxDynamicSharedMemorySize, EDGE_SMEM);
    cudaFuncSetAttribute(k_node, cudaFuncAttributeMaxDynamicSharedMemorySize, NODE_SMEM);

    k_zero<<<512, 256>>>();
    k_pre<<<(N_NODES + 31) / 32, 256>>>(ns, W1f, W1r);
    k_edge<<<N_EDGES / 128, 256, EDGE_SMEM>>>(ef, W1f, b1f, W2f, b2f,
                                              W1r, b1r, W2r, b2r, from_idx, to_idx);
    k_node<<<(N_NODES + 63) / 64, 256, NODE_SMEM>>>(ns, Wn1, bn1, Wn2, bn2, out);
}

// round 2
// speedup vs baseline: 1.0425x; 1.0425x over previous
#include <cuda_runtime.h>
#include <cstdint>
#include <cstddef>

#define N_NODES 50000
#define N_EDGES 800000
#define D_NODE  64
#define D_MSG   128

typedef unsigned long long ull;

// Scratch (device globals; no allocation in kernel_launch).
// g_P layout per node: [0:128)=ns@W1_f[0:64]     (pair with from, fwd)
//                      [128:256)=ns@W1_f[64:128] (pair with to, fwd)
//                      [256:384)=ns@W1_r[0:64]   (pair with to, rev)
//                      [384:512)=ns@W1_r[64:128] (pair with from, rev)
__device__ float g_P[(size_t)N_NODES * 512];
__device__ float g_agg[(size_t)N_NODES * D_MSG];

__device__ __forceinline__ void red_add_v4(float* p, float a, float b, float c, float d) {
    asm volatile("red.global.add.v4.f32 [%0], {%1, %2, %3, %4};"
                 :: "l"(p), "f"(a), "f"(b), "f"(c), "f"(d) : "memory");
}

// ---- packed f32x2 helpers (Blackwell FFMA2: 2x fma-pipe throughput) ----
__device__ __forceinline__ void ffma2(ull& acc, ull x2, ull w2) {
    asm("fma.rn.f32x2 %0, %1, %2, %0;" : "+l"(acc) : "l"(x2), "l"(w2));
}
__device__ __forceinline__ ull dup2(float x) {
    ull r; asm("mov.b64 %0, {%1, %1};" : "=l"(r) : "f"(x)); return r;
}
__device__ __forceinline__ float2 unpack2(ull v) {
    float2 r; asm("mov.b64 {%0, %1}, %2;" : "=f"(r.x), "=f"(r.y) : "l"(v)); return r;
}

// ---------------------------------------------------------------------------
// Zero the aggregation buffer (graph-replay safe: done every launch).
// ---------------------------------------------------------------------------
__global__ void k_zero() {
    const int n4 = N_NODES * D_MSG / 4;
    float4 z = make_float4(0.f, 0.f, 0.f, 0.f);
    for (int i = blockIdx.x * blockDim.x + threadIdx.x; i < n4; i += gridDim.x * blockDim.x)
        ((float4*)g_agg)[i] = z;
}

// ---------------------------------------------------------------------------
// Node pre-projections: g_P = ns @ [W1_f[0:64] | W1_f[64:128] | W1_r[0:64] | W1_r[64:128]]
// ---------------------------------------------------------------------------
__global__ __launch_bounds__(256) void k_pre(const float* __restrict__ ns,
                                             const float* __restrict__ W1f,
                                             const float* __restrict__ W1r) {
    __shared__ float s_x[32 * 64];    // 8 KB
    __shared__ float s_w[64 * 128];   // 32 KB
    const int t = threadIdx.x;
    const int base = blockIdx.x * 32;

    for (int i = t; i < 512; i += 256) {
        int n = base + i / 16;
        float4 v = make_float4(0.f, 0.f, 0.f, 0.f);
        if (n < N_NODES) v = ((const float4*)ns)[(size_t)n * 16 + (i % 16)];
        ((float4*)s_x)[i] = v;
    }

    const int tx = t % 32, ty = t / 32;
    const int j0 = tx * 4, n0 = ty * 4;

    for (int m = 0; m < 4; ++m) {
        __syncthreads();
        const float* Wsrc = ((m < 2) ? W1f : W1r) + (size_t)(m & 1) * 64 * 128;
        for (int i = t; i < 2048; i += 256)
            ((float4*)s_w)[i] = ((const float4*)Wsrc)[i];
        __syncthreads();

        ull acc[4][2] = {};
        for (int k4 = 0; k4 < 16; ++k4) {
            float4 xv[4];
            #pragma unroll
            for (int n = 0; n < 4; ++n)
                xv[n] = *(const float4*)&s_x[(n0 + n) * 64 + k4 * 4];
            #pragma unroll
            for (int kk = 0; kk < 4; ++kk) {
                ulonglong2 w = *(const ulonglong2*)&s_w[(k4 * 4 + kk) * 128 + j0];
                #pragma unroll
                for (int n = 0; n < 4; ++n) {
                    ull x2 = dup2(((const float*)&xv[n])[kk]);
                    ffma2(acc[n][0], x2, w.x);
                    ffma2(acc[n][1], x2, w.y);
                }
            }
        }
        #pragma unroll
        for (int n = 0; n < 4; ++n) {
            int gn = base + n0 + n;
            if (gn < N_NODES) {
                float2 a = unpack2(acc[n][0]), b = unpack2(acc[n][1]);
                *(float4*)&g_P[(size_t)gn * 512 + m * 128 + j0] =
                    make_float4(a.x, a.y, b.x, b.y);
            }
        }
    }
}

// ---------------------------------------------------------------------------
// Edge kernel: per 128-edge tile, both directions.
//   h = relu(P_A[idxA] + P_B[idxB] + ef @ W1[128:192] + b1)
//   msg = h @ W2 + b2 ; red-add into g_agg[idxB]
// 256 threads; each thread owns an 8-edge x 8-col register tile (FFMA2 pairs).
// ---------------------------------------------------------------------------
#define EDGE_SMEM (49152 * 4 + 256 * 4)
__global__ __launch_bounds__(256) void k_edge(
    const float* __restrict__ ef,
    const float* __restrict__ W1f, const float* __restrict__ b1f,
    const float* __restrict__ W2f, const float* __restrict__ b2f,
    const float* __restrict__ W1r, const float* __restrict__ b1r,
    const float* __restrict__ W2r, const float* __restrict__ b2r,
    const int* __restrict__ from_idx, const int* __restrict__ to_idx) {
    extern __shared__ float sm[];
    float* s_ef = sm;              // 128x64   = 8192
    float* s_w1 = sm + 8192;       // 64x128   = 8192
    float* s_w2 = sm + 16384;      // 128x128  = 16384
    float* s_h  = sm + 32768;      // 128x128  = 16384
    int*   s_from = (int*)(sm + 49152);
    int*   s_to   = s_from + 128;

    const int t = threadIdx.x;
    const int ebase = blockIdx.x * 128;   // N_EDGES % 128 == 0

    for (int i = t; i < 2048; i += 256)
        ((float4*)s_ef)[i] = ((const float4*)(ef + (size_t)ebase * 64))[i];
    if (t < 128) s_from[t] = from_idx[ebase + t];
    else         s_to[t - 128] = to_idx[ebase + t - 128];

    const int tx = t % 16, ty = t / 16;
    const int j0 = tx * 8, e0 = ty * 8;

    for (int dir = 0; dir < 2; ++dir) {
        const float* W1 = dir ? W1r : W1f;
        const float* W2 = dir ? W2r : W2f;
        const float* b1 = dir ? b1r : b1f;
        const float* b2 = dir ? b2r : b2f;
        const int offA = dir * 256;

        __syncthreads();   // previous phase done before weights overwritten
        for (int i = t; i < 2048; i += 256)
            ((float4*)s_w1)[i] = ((const float4*)(W1 + 128 * 128))[i];
        for (int i = t; i < 4096; i += 256)
            ((float4*)s_w2)[i] = ((const float4*)W2)[i];
        __syncthreads();

        // ---- layer 1: ef @ W1c (FFMA2) ----
        ull acc[8][4] = {};
        for (int k4 = 0; k4 < 16; ++k4) {
            float4 xv[8];
            #pragma unroll
            for (int e = 0; e < 8; ++e)
                xv[e] = *(const float4*)&s_ef[(e0 + e) * 64 + k4 * 4];
            #pragma unroll
            for (int kk = 0; kk < 4; ++kk) {
                ulonglong2 wa = *(const ulonglong2*)&s_w1[(k4 * 4 + kk) * 128 + j0];
                ulonglong2 wb = *(const ulonglong2*)&s_w1[(k4 * 4 + kk) * 128 + j0 + 4];
                #pragma unroll
                for (int e = 0; e < 8; ++e) {
                    ull x2 = dup2(((const float*)&xv[e])[kk]);
                    ffma2(acc[e][0], x2, wa.x);
                    ffma2(acc[e][1], x2, wa.y);
                    ffma2(acc[e][2], x2, wb.x);
                    ffma2(acc[e][3], x2, wb.y);
                }
            }
        }
        // ---- add gathered node pre-projections + bias, relu, -> smem ----
        float4 bb0 = *(const float4*)&b1[j0];
        float4 bb1 = *(const float4*)&b1[j0 + 4];
        #pragma unroll
        for (int e = 0; e < 8; ++e) {
            int ee = e0 + e;
            int ia = dir ? s_to[ee] : s_from[ee];
            int ib = dir ? s_from[ee] : s_to[ee];
            const float* pA = g_P + (size_t)ia * 512 + offA + j0;
            const float* pB = g_P + (size_t)ib * 512 + offA + 128 + j0;
            float4 a0 = *(const float4*)pA, a1 = *(const float4*)(pA + 4);
            float4 c0 = *(const float4*)pB, c1 = *(const float4*)(pB + 4);
            float v[8];
            #pragma unroll
            for (int p = 0; p < 4; ++p) {
                float2 u = unpack2(acc[e][p]);
                v[2 * p] = u.x; v[2 * p + 1] = u.y;
            }
            float r0 = fmaxf(v[0] + a0.x + c0.x + bb0.x, 0.f);
            float r1 = fmaxf(v[1] + a0.y + c0.y + bb0.y, 0.f);
            float r2 = fmaxf(v[2] + a0.z + c0.z + bb0.z, 0.f);
            float r3 = fmaxf(v[3] + a0.w + c0.w + bb0.w, 0.f);
            float r4 = fmaxf(v[4] + a1.x + c1.x + bb1.x, 0.f);
            float r5 = fmaxf(v[5] + a1.y + c1.y + bb1.y, 0.f);
            float r6 = fmaxf(v[6] + a1.z + c1.z + bb1.z, 0.f);
            float r7 = fmaxf(v[7] + a1.w + c1.w + bb1.w, 0.f);
            *(float4*)&s_h[ee * 128 + j0]     = make_float4(r0, r1, r2, r3);
            *(float4*)&s_h[ee * 128 + j0 + 4] = make_float4(r4, r5, r6, r7);
        }
        __syncthreads();

        // ---- layer 2: h @ W2 (FFMA2) ----
        ull acc2[8][4] = {};
        for (int k4 = 0; k4 < 32; ++k4) {
            float4 xv[8];
            #pragma unroll
            for (int e = 0; e < 8; ++e)
                xv[e] = *(const float4*)&s_h[(e0 + e) * 128 + k4 * 4];
            #pragma unroll
            for (int kk = 0; kk < 4; ++kk) {
                ulonglong2 wa = *(const ulonglong2*)&s_w2[(k4 * 4 + kk) * 128 + j0];
                ulonglong2 wb = *(const ulonglong2*)&s_w2[(k4 * 4 + kk) * 128 + j0 + 4];
                #pragma unroll
                for (int e = 0; e < 8; ++e) {
                    ull x2 = dup2(((const float*)&xv[e])[kk]);
                    ffma2(acc2[e][0], x2, wa.x);
                    ffma2(acc2[e][1], x2, wa.y);
                    ffma2(acc2[e][2], x2, wb.x);
                    ffma2(acc2[e][3], x2, wb.y);
                }
            }
        }
        // ---- scatter (msg + b2) into g_agg[ib] ----
        float4 cb0 = *(const float4*)&b2[j0];
        float4 cb1 = *(const float4*)&b2[j0 + 4];
        #pragma unroll
        for (int e = 0; e < 8; ++e) {
            int ee = e0 + e;
            int ib = dir ? s_from[ee] : s_to[ee];
            float* p = g_agg + (size_t)ib * 128 + j0;
            float v[8];
            #pragma unroll
            for (int q = 0; q < 4; ++q) {
                float2 u = unpack2(acc2[e][q]);
                v[2 * q] = u.x; v[2 * q + 1] = u.y;
            }
            red_add_v4(p,     v[0] + cb0.x, v[1] + cb0.y, v[2] + cb0.z, v[3] + cb0.w);
            red_add_v4(p + 4, v[4] + cb1.x, v[5] + cb1.y, v[6] + cb1.z, v[7] + cb1.w);
        }
    }
}

// ---------------------------------------------------------------------------
// Node update: out = ns + relu([agg | ns] @ Wn1 + bn1) @ Wn2 + bn2
// ---------------------------------------------------------------------------
#define NODE_SMEM (53248 * 4)
__global__ __launch_bounds__(256) void k_node(
    const float* __restrict__ ns,
    const float* __restrict__ Wn1, const float* __restrict__ bn1,
    const float* __restrict__ Wn2, const float* __restrict__ bn2,
    float* __restrict__ out) {
    extern __shared__ float sm[];
    float* s_x  = sm;             // 64x192 = 12288
    float* s_w1 = sm + 12288;     // 192x128 = 24576
    float* s_h  = sm + 36864;     // 64x128 = 8192
    float* s_w2 = sm + 45056;     // 128x64 = 8192

    const int t = threadIdx.x;
    const int base = blockIdx.x * 64;

    for (int i = t; i < 3072; i += 256) {
        int n = i / 48, c4 = i % 48;
        int gn = base + n;
        float4 v = make_float4(0.f, 0.f, 0.f, 0.f);
        if (gn < N_NODES) {
            if (c4 < 32) v = ((const float4*)g_agg)[(size_t)gn * 32 + c4];
            else         v = ((const float4*)ns)[(size_t)gn * 16 + (c4 - 32)];
        }
        ((float4*)s_x)[i] = v;
    }
    for (int i = t; i < 6144; i += 256) ((float4*)s_w1)[i] = ((const float4*)Wn1)[i];
    for (int i = t; i < 2048; i += 256) ((float4*)s_w2)[i] = ((const float4*)Wn2)[i];
    __syncthreads();

    // GEMM1: h[64][128] (FFMA2)
    {
        const int tx = t % 32, ty = t / 32;
        const int j0 = tx * 4, n0 = ty * 8;
        ull acc[8][2] = {};
        for (int k4 = 0; k4 < 48; ++k4) {
            float4 xv[8];
            #pragma unroll
            for (int n = 0; n < 8; ++n)
                xv[n] = *(const float4*)&s_x[(n0 + n) * 192 + k4 * 4];
            #pragma unroll
            for (int kk = 0; kk < 4; ++kk) {
                ulonglong2 w = *(const ulonglong2*)&s_w1[(k4 * 4 + kk) * 128 + j0];
                #pragma unroll
                for (int n = 0; n < 8; ++n) {
                    ull x2 = dup2(((const float*)&xv[n])[kk]);
                    ffma2(acc[n][0], x2, w.x);
                    ffma2(acc[n][1], x2, w.y);
                }
            }
        }
        float4 bb = *(const float4*)&bn1[j0];
        #pragma unroll
        for (int n = 0; n < 8; ++n) {
            float2 a = unpack2(acc[n][0]), b = unpack2(acc[n][1]);
            *(float4*)&s_h[(n0 + n) * 128 + j0] = make_float4(
                fmaxf(a.x + bb.x, 0.f), fmaxf(a.y + bb.y, 0.f),
                fmaxf(b.x + bb.z, 0.f), fmaxf(b.y + bb.w, 0.f));
        }
    }
    __syncthreads();

    // GEMM2 + residual: out[64][64] (FFMA2)
    {
        const int tx = t % 16, ty = t / 16;
        const int j0 = tx * 4, n0 = ty * 4;
        ull acc[4][2] = {};
        for (int k4 = 0; k4 < 32; ++k4) {
            float4 xv[4];
            #pragma unroll
            for (int n = 0; n < 4; ++n)
                xv[n] = *(const float4*)&s_h[(n0 + n) * 128 + k4 * 4];
            #pragma unroll
            for (int kk = 0; kk < 4; ++kk) {
                ulonglong2 w = *(const ulonglong2*)&s_w2[(k4 * 4 + kk) * 64 + j0];
                #pragma unroll
                for (int n = 0; n < 4; ++n) {
                    ull x2 = dup2(((const float*)&xv[n])[kk]);
                    ffma2(acc[n][0], x2, w.x);
                    ffma2(acc[n][1], x2, w.y);
                }
            }
        }
        float4 bb = *(const float4*)&bn2[j0];
        #pragma unroll
        for (int n = 0; n < 4; ++n) {
            int gn = base + n0 + n;
            if (gn < N_NODES) {
                float2 a = unpack2(acc[n][0]), b = unpack2(acc[n][1]);
                float4 r = ((const float4*)ns)[(size_t)gn * 16 + j0 / 4];
                ((float4*)out)[(size_t)gn * 16 + j0 / 4] = make_float4(
                    r.x + a.x + bb.x, r.y + a.y + bb.y,
                    r.z + b.x + bb.z, r.w + b.y + bb.w);
            }
        }
    }
}

// ---------------------------------------------------------------------------
extern "C" void kernel_launch(void* const* d_in, const int* in_sizes, int n_in,
                              void* d_out, int out_size) {
    const float* ns  = (const float*)d_in[0];
    const float* ef  = (const float*)d_in[1];
    const float* W1f = (const float*)d_in[2];
    const float* b1f = (const float*)d_in[3];
    const float* W2f = (const float*)d_in[4];
    const float* b2f = (const float*)d_in[5];
    const float* W1r = (const float*)d_in[6];
    const float* b1r = (const float*)d_in[7];
    const float* W2r = (const float*)d_in[8];
    const float* b2r = (const float*)d_in[9];
    const float* Wn1 = (const float*)d_in[10];
    const float* bn1 = (const float*)d_in[11];
    const float* Wn2 = (const float*)d_in[12];
    const float* bn2 = (const float*)d_in[13];
    const int* from_idx = (const int*)d_in[14];
    const int* to_idx   = (const int*)d_in[15];
    float* out = (float*)d_out;

    cudaFuncSetAttribute(k_edge, cudaFuncAttributeMaxDynamicSharedMemorySize, EDGE_SMEM);
    cudaFuncSetAttribute(k_node, cudaFuncAttributeMaxDynamicSharedMemorySize, NODE_SMEM);

    k_zero<<<512, 256>>>();
    k_pre<<<(N_NODES + 31) / 32, 256>>>(ns, W1f, W1r);
    k_edge<<<N_EDGES / 128, 256, EDGE_SMEM>>>(ef, W1f, b1f, W2f, b2f,
                                              W1r, b1r, W2r, b2r, from_idx, to_idx);
    k_node<<<(N_NODES + 63) / 64, 256, NODE_SMEM>>>(ns, Wn1, bn1, Wn2, bn2, out);
}